// round 14
// baseline (speedup 1.0000x reference)
#include <cuda_runtime.h>
#include <math.h>
#include <stdint.h>

#define B 16
#define T 2048
#define D 512
#define C 512
#define KW 11
#define KHALF 5
#define THRESH 0.9f
#define MAXTOK 128
#define EPS_F 2e-5f
#define TILE 32                   // t-tile per k_logit block
#define NROWS (TILE + 2*KHALF)    // 42 staged rows
#define SM_FLOATS (NROWS * D)     // 21504 floats = 86016 B

// ---------------- scratch (no allocation allowed) ----------------
__device__ __align__(16) float g_weff[KW * D];
__device__ float g_beff;
__device__ float g_logit[B * T];
__device__ __align__(16) float g_anorm[B * T];  // alpha_norm
__device__ int   g_fire_t[B * MAXTOK];          // fire time of token n
__device__ float g_fak1[B * MAXTOK];            // ak1 at fire n
__device__ float g_fak2[B * MAXTOK];            // ak2 at fire n
__device__ int   g_nf[B];                       // number of fired tokens

// ---- packed f32x2 helpers (sm_103a) ----
__device__ __forceinline__ unsigned long long pack2(float a, float b) {
    unsigned long long r;
    asm("mov.b64 %0, {%1, %2};" : "=l"(r) : "f"(a), "f"(b));
    return r;
}
__device__ __forceinline__ void unpack2(unsigned long long v, float& a, float& b) {
    asm("mov.b64 {%0, %1}, %2;" : "=f"(a), "=f"(b) : "l"(v));
}
#define FMA2(accv, av, bv) \
    asm("fma.rn.f32x2 %0, %1, %2, %0;" : "+l"(accv) : "l"(av), "l"(bv))

__device__ __forceinline__ uint32_t smem_u32(const void* p) {
    uint32_t a;
    asm("{ .reg .u64 t; cvta.to.shared.u64 t, %1; cvt.u32.u64 %0, t; }"
        : "=r"(a) : "l"(p));
    return a;
}

// ---------------- kernel 0: no-op (aligns ncu capture onto alpha_scan) ------
__global__ void k_nop() {}

// ---------------- kernel 1: fold projection into conv weights ----------------
__global__ void k_weff(const float* __restrict__ conv_w,
                       const float* __restrict__ conv_b,
                       const float* __restrict__ proj_w,
                       const float* __restrict__ proj_b) {
    int wid  = blockIdx.x * (blockDim.x >> 5) + (threadIdx.x >> 5);
    int lane = threadIdx.x & 31;
    if (wid < KW * D) {
        const float* row = conv_w + (size_t)wid * C;
        float s = 0.f;
        #pragma unroll 4
        for (int c = lane; c < C; c += 32) s += row[c] * proj_w[c];
        #pragma unroll
        for (int o = 16; o; o >>= 1) s += __shfl_down_sync(0xffffffffu, s, o);
        if (lane == 0) g_weff[wid] = s;
    } else if (wid == KW * D) {
        float s = 0.f;
        for (int c = lane; c < C; c += 32) s += conv_b[c] * proj_w[c];
        #pragma unroll
        for (int o = 16; o; o >>= 1) s += __shfl_down_sync(0xffffffffu, s, o);
        if (lane == 0) g_beff = s + proj_b[0];
    }
}

// ---------------- kernel 2: conv logits — cp.async staged tile ---------------
__global__ void __launch_bounds__(256, 2)
k_logit(const float* __restrict__ eouts) {
    extern __shared__ float sm[];           // SM_FLOATS floats
    int b = blockIdx.y;
    int t0 = blockIdx.x * TILE;
    int tid = threadIdx.x;  // 0..255

    // ---- stage: 42 rows x 128 chunks of 16B, all loads in flight ----
    {
        uint32_t sbase = smem_u32(sm);
        #pragma unroll
        for (int c = tid; c < NROWS * 128; c += 256) {
            int row = c >> 7;
            int off16 = c & 127;
            int t = t0 + row - KHALF;
            uint32_t saddr = sbase + c * 16;
            if (t >= 0 && t < T) {
                const float* g = eouts + ((size_t)b * T + t) * D + off16 * 4;
                asm volatile("cp.async.cg.shared.global [%0], [%1], 16;"
                             :: "r"(saddr), "l"(g));
            } else {
                asm volatile("st.shared.v4.b32 [%0], {%1, %1, %1, %1};"
                             :: "r"(saddr), "r"(0u));
            }
        }
        asm volatile("cp.async.commit_group;");
        asm volatile("cp.async.wait_group 0;");
    }
    __syncthreads();

    unsigned long long w[KW];
    #pragma unroll
    for (int k = 0; k < KW; k++) {
        float2 wv = ((const float2*)(g_weff + k * D))[tid];
        w[k] = pack2(wv.x, wv.y);
    }

    unsigned long long acc[TILE];
    unsigned long long z = pack2(0.f, 0.f);
    #pragma unroll
    for (int i = 0; i < TILE; i++) acc[i] = z;

    const unsigned long long* sm2 = (const unsigned long long*)sm;
    #pragma unroll
    for (int tt = 0; tt < NROWS; tt++) {
        unsigned long long vp = sm2[tt * 256 + tid];   // LDS.64, CF
        #pragma unroll
        for (int k = 0; k < KW; k++) {
            int i = tt - k;
            if (i >= 0 && i < TILE) FMA2(acc[i], vp, w[k]);
        }
    }
    __syncthreads();   // staging data consumed; reuse smem for reduction

    float* r  = sm;                 // [TILE][257]
    float* r2 = sm + TILE * 257;    // [TILE][9]
    #pragma unroll
    for (int i = 0; i < TILE; i++) {
        float lo, hi;
        unpack2(acc[i], lo, hi);
        r[i * 257 + tid] = lo + hi;
    }
    __syncthreads();
    {
        int i = tid & 31, seg = tid >> 5;   // 32 outputs x 8 segments of 32
        float sum = 0.f;
        #pragma unroll
        for (int j = 0; j < 32; j++)
            sum += r[i * 257 + seg * 32 + j];
        r2[i * 9 + seg] = sum;
    }
    __syncthreads();
    if (tid < TILE) {
        float tot = g_beff;
        #pragma unroll
        for (int j = 0; j < 8; j++) tot += r2[tid * 9 + j];
        g_logit[b * T + t0 + tid] = tot;
    }
}

// ---------------- kernel 3: alpha + prefix + float-fast fire sweep -----------
__global__ void k_alpha_scan(float* __restrict__ out_alpha,
                             const int* __restrict__ elens,
                             const int* __restrict__ ylens) {
    int b = blockIdx.x;
    int tid = threadIdx.x;
    int lane = tid & 31, wid = tid >> 5;

    __shared__ float  sA[T];        // alpha_norm
    __shared__ double sS[T];        // inclusive prefix of alpha_norm (exact)
    __shared__ float  sSf[T];       // float mirror of sS (fast compares)
    __shared__ double sT1[T];       // 1.0 - (double)alpha_norm
    __shared__ double sWarp[32];
    __shared__ int    s_fire_t[MAXTOK];
    __shared__ float  s_ak1[MAXTOK], s_ak2[MAXTOK];
    __shared__ float  s_asum;

    int el = elens[b];
    int yl = ylens[b];

    // --- step 1: sigmoid alphas + block reduce for asum ---
    float a0, a1;
    {
        double local = 0.0;
        #pragma unroll
        for (int rep = 0; rep < 2; rep++) {
            int t = tid + rep * 1024;
            float lg = g_logit[b * T + t];
            float a = 1.f / (1.f + expf(-lg));
            if (rep == 0) a0 = a; else a1 = a;
            local += (double)a;
        }
        #pragma unroll
        for (int o = 16; o; o >>= 1) local += __shfl_down_sync(0xffffffffu, local, o);
        if (lane == 0) sWarp[wid] = local;
        __syncthreads();
        if (wid == 0) {
            double v = sWarp[lane];
            #pragma unroll
            for (int o = 16; o; o >>= 1) v += __shfl_down_sync(0xffffffffu, v, o);
            if (lane == 0) s_asum = (float)v;
        }
        __syncthreads();
    }
    float asum = s_asum;
    float ylf = (float)yl;

    // --- step 2: alpha_norm + (1 - a) table ---
    {
        int t0 = tid, t1 = tid + 1024;
        float an0 = a0 / asum * ylf;
        float an1 = a1 / asum * ylf;
        sA[t0] = an0; sA[t1] = an1;
        sT1[t0] = 1.0 - (double)an0;
        sT1[t1] = 1.0 - (double)an1;
        out_alpha[b * T + t0] = a0;  out_alpha[b * T + t1] = a1;
        g_anorm[b * T + t0] = an0;   g_anorm[b * T + t1] = an1;
    }
    __syncthreads();

    // --- step 3: block inclusive prefix scan (double) + float mirror ---
    {
        float e0 = sA[2 * tid], e1 = sA[2 * tid + 1];
        double my = (double)e0 + (double)e1;
        double v = my;
        #pragma unroll
        for (int o = 1; o < 32; o <<= 1) {
            double n = __shfl_up_sync(0xffffffffu, v, o);
            if (lane >= o) v += n;
        }
        if (lane == 31) sWarp[wid] = v;
        __syncthreads();
        if (wid == 0) {
            double w = sWarp[lane];
            #pragma unroll
            for (int o = 1; o < 32; o <<= 1) {
                double n = __shfl_up_sync(0xffffffffu, w, o);
                if (lane >= o) w += n;
            }
            sWarp[lane] = w;
        }
        __syncthreads();
        double base = (wid ? sWarp[wid - 1] : 0.0) + (v - my);
        double p0 = base + (double)e0;
        double p1 = p0 + (double)e1;
        sS[2 * tid]     = p0;
        sS[2 * tid + 1] = p1;
        sSf[2 * tid]     = (float)p0;
        sSf[2 * tid + 1] = (float)p1;
    }
    __syncthreads();

    // --- step 4: warp 0 — float fast-path sweep with exact double guard ---
    // Invariant: committed fires are EXACTLY those of the pure-double sweep.
    //   sSf[t] <  th_f - EPS  =>  sS[t] <  th_d  (certain miss)
    //   sSf[t] >= th_f + EPS  =>  sS[t] >= th_d  (certain hit)
    // ambiguity band resolved with exact doubles (rare).
    if (wid == 0) {
        double th_d = (double)THRESH;
        float  th_f = THRESH;
        int pos = 0, ntok = 0;
        while (ntok < yl && pos < el) {
            int t = pos + lane;
            int tc = (t < T) ? t : (T - 1);
            float sv = sSf[tc];
            bool in = (t < el);
            unsigned mlo = __ballot_sync(~0u, in && (sv >= th_f - EPS_F));
            if (!mlo) { pos += 32; continue; }
            unsigned mhi = __ballot_sync(~0u, in && (sv >= th_f + EPS_F));
            int flo = pos + __ffs(mlo) - 1;
            int f;
            if (mhi && (__ffs(mhi) == __ffs(mlo))) {
                f = flo;                       // certain: matches double decision
            } else {
                // exact resolution from flo (positions < flo are certain misses)
                f = -1;
                for (int bb = flo; bb < el; bb += 32) {
                    int u = bb + lane;
                    int uc = (u < T) ? u : (T - 1);
                    unsigned me = __ballot_sync(~0u, (u < el) && (sS[uc] >= th_d));
                    if (me) { f = bb + __ffs(me) - 1; break; }
                }
                if (f < 0) break;
            }
            // exact output math (identical to pure-double version)
            float a = sA[f];
            float acc = (float)(sS[f] - th_d) + THRESH;
            float ak1 = 1.f - acc;
            float ak2 = a - ak1;
            if (lane == 0) {
                s_fire_t[ntok] = f;
                s_ak1[ntok] = ak1;
                s_ak2[ntok] = ak2;
            }
            th_d += sT1[f];              // exact threshold (only FP64 on chain)
            th_f = (float)th_d;          // refreshed: |th_f - th_d| <= ulp
            pos = f + 1;
            ntok++;
        }
        __syncwarp();
        if (lane == 0) g_nf[b] = ntok;
        for (int i = lane; i < ntok; i += 32) {
            g_fire_t[b * MAXTOK + i] = s_fire_t[i];
            g_fak1[b * MAXTOK + i] = s_ak1[i];
            g_fak2[b * MAXTOK + i] = s_ak2[i];
        }
    }
}

// ---------------- kernel 4: fused aws rows + fired reductions ----------------
// grid (L+1, B, 2): z=0 -> fired token n=x (x<L); z=1 -> aws row r=x.
__global__ void __launch_bounds__(1024)
k_out(const float* __restrict__ eouts, float* __restrict__ fired,
      float* __restrict__ aws, const int* __restrict__ elens,
      const int* __restrict__ ylens, int L) {
    int b = blockIdx.y;
    int nf = g_nf[b];

    if (blockIdx.z == 1) {
        // ---- aws row r ----
        int r = blockIdx.x;          // 0..L
        int tid = threadIdx.x;
        float4* row = (float4*)(aws + ((size_t)b * (L + 1) + r) * T);
        if (tid >= T / 4) return;
        if (r > nf) {
            row[tid] = make_float4(0.f, 0.f, 0.f, 0.f);
            return;
        }
        int el = elens[b];
        int yl = ylens[b];
        int   fprev = (r > 0) ? g_fire_t[b * MAXTOK + r - 1] : -1;
        float vprev = (r > 0) ? g_fak2[b * MAXTOK + r - 1] : 0.f;
        int   fr   = (r < nf) ? g_fire_t[b * MAXTOK + r] : -2;
        float vak1 = (r < nf) ? g_fak1[b * MAXTOK + r] : 0.f;
        int aEnd = (r < nf) ? fr : ((r < yl) ? el : fprev);

        const float4* an4 = (const float4*)(g_anorm + b * T);
        float4 a4 = an4[tid];
        float av[4] = {a4.x, a4.y, a4.z, a4.w};
        float ov[4];
        int t0 = 4 * tid;
        #pragma unroll
        for (int j = 0; j < 4; j++) {
            int t = t0 + j;
            float v = 0.f;
            if (t > fprev && t < aEnd) v = av[j];
            else if (t == fprev)       v = vprev;
            else if (t == fr)          v = vak1;
            ov[j] = v;
        }
        row[tid] = make_float4(ov[0], ov[1], ov[2], ov[3]);
        return;
    }

    // ---- fired token n (8-phase) ----
    int n = blockIdx.x;
    if (n >= L) return;
    int d  = threadIdx.x & 127;   // float4 slice of D
    int ph = threadIdx.x >> 7;    // 0..7 time phase

    if (n >= nf) {                // zero-fill unused rows
        if (ph == 0)
            ((float4*)(fired + ((size_t)b * L + n) * D))[d] =
                make_float4(0.f, 0.f, 0.f, 0.f);
        return;
    }

    int e = g_fire_t[b * MAXTOK + n];
    float c1 = g_fak1[b * MAXTOK + n];
    int s; float c0;
    if (n == 0) { s = -1; c0 = 0.f; }
    else { s = g_fire_t[b * MAXTOK + n - 1]; c0 = g_fak2[b * MAXTOK + n - 1]; }

    const float* an = g_anorm + b * T;
    const float4* eb = (const float4*)(eouts + (size_t)b * T * D);

    int t0 = (s >= 0) ? s : 0;
    float4 acc = make_float4(0.f, 0.f, 0.f, 0.f);
    #pragma unroll 2
    for (int t = t0 + ph; t <= e; t += 8) {
        float w = (t == e) ? c1 : ((t == s) ? c0 : an[t]);
        float4 v = eb[(size_t)t * 128 + d];
        acc.x += w * v.x; acc.y += w * v.y;
        acc.z += w * v.z; acc.w += w * v.w;
    }

    __shared__ float4 sAcc[1024];
    sAcc[threadIdx.x] = acc;
    __syncthreads();
    if (ph == 0) {
        #pragma unroll
        for (int p = 1; p < 8; p++) {
            float4 a = sAcc[p * 128 + d];
            acc.x += a.x; acc.y += a.y; acc.z += a.z; acc.w += a.w;
        }
        ((float4*)(fired + ((size_t)b * L + n) * D))[d] = acc;
    }
}

// ---------------- launch ------------------------------------------------------
extern "C" void kernel_launch(void* const* d_in, const int* in_sizes, int n_in,
                              void* d_out, int out_size) {
    const float* eouts  = (const float*)d_in[0];
    const float* conv_w = (const float*)d_in[1];
    const float* conv_b = (const float*)d_in[2];
    const float* proj_w = (const float*)d_in[3];
    const float* proj_b = (const float*)d_in[4];
    const int*   elens  = (const int*)d_in[5];
    const int*   ylens  = (const int*)d_in[6];

    // out = concat(fired[B,L,D], alpha[B,T], aws[B,1,L+1,T])
    int L = (out_size - 2 * B * T) / (B * D + B * T);

    float* out   = (float*)d_out;
    float* fired = out;
    float* alpha = out + (size_t)B * L * D;
    float* aws   = alpha + (size_t)B * T;

    const int SMEM_BYTES = SM_FLOATS * sizeof(float);  // 86016
    cudaFuncSetAttribute(k_logit,
                         cudaFuncAttributeMaxDynamicSharedMemorySize, SMEM_BYTES);

    k_weff<<<(KW * D + 1 + 7) / 8, 256>>>(conv_w, conv_b, proj_w, proj_b);
    k_logit<<<dim3(T / TILE, B), 256, SMEM_BYTES>>>(eouts);
    k_nop<<<1, 32>>>();
    k_alpha_scan<<<B, 1024>>>(alpha, elens, ylens);   // 4th launch -> profiled
    k_out<<<dim3(L + 1, B, 2), 1024>>>(eouts, fired, aws, elens, ylens, L);
}

// round 15
// speedup vs baseline: 1.1204x; 1.1204x over previous
#include <cuda_runtime.h>
#include <math.h>
#include <stdint.h>

#define B 16
#define T 2048
#define D 512
#define C 512
#define KW 11
#define KHALF 5
#define THRESH 0.9f
#define MAXTOK 128
#define TILE 32                   // t-tile per k_logit block
#define NROWS (TILE + 2*KHALF)    // 42 staged rows
#define SM_FLOATS (NROWS * D)     // 21504 floats = 86016 B

// ---------------- scratch (no allocation allowed) ----------------
__device__ __align__(16) float g_weff[KW * D];
__device__ float g_beff;
__device__ float g_logit[B * T];
__device__ __align__(16) float g_anorm[B * T];  // alpha_norm
__device__ int   g_fire_t[B * MAXTOK];          // fire time of token n
__device__ float g_fak1[B * MAXTOK];            // ak1 at fire n
__device__ float g_fak2[B * MAXTOK];            // ak2 at fire n
__device__ int   g_nf[B];                       // number of fired tokens

// ---- packed f32x2 helpers (sm_103a) ----
__device__ __forceinline__ unsigned long long pack2(float a, float b) {
    unsigned long long r;
    asm("mov.b64 %0, {%1, %2};" : "=l"(r) : "f"(a), "f"(b));
    return r;
}
__device__ __forceinline__ void unpack2(unsigned long long v, float& a, float& b) {
    asm("mov.b64 {%0, %1}, %2;" : "=f"(a), "=f"(b) : "l"(v));
}
#define FMA2(accv, av, bv) \
    asm("fma.rn.f32x2 %0, %1, %2, %0;" : "+l"(accv) : "l"(av), "l"(bv))

__device__ __forceinline__ uint32_t smem_u32(const void* p) {
    uint32_t a;
    asm("{ .reg .u64 t; cvta.to.shared.u64 t, %1; cvt.u32.u64 %0, t; }"
        : "=r"(a) : "l"(p));
    return a;
}

// ---------------- kernel 0: no-op (aligns ncu capture onto alpha_scan) ------
__global__ void k_nop() {}

// ---------------- kernel 1: fold projection into conv weights ----------------
__global__ void k_weff(const float* __restrict__ conv_w,
                       const float* __restrict__ conv_b,
                       const float* __restrict__ proj_w,
                       const float* __restrict__ proj_b) {
    int wid  = blockIdx.x * (blockDim.x >> 5) + (threadIdx.x >> 5);
    int lane = threadIdx.x & 31;
    if (wid < KW * D) {
        const float* row = conv_w + (size_t)wid * C;
        float s = 0.f;
        #pragma unroll 4
        for (int c = lane; c < C; c += 32) s += row[c] * proj_w[c];
        #pragma unroll
        for (int o = 16; o; o >>= 1) s += __shfl_down_sync(0xffffffffu, s, o);
        if (lane == 0) g_weff[wid] = s;
    } else if (wid == KW * D) {
        float s = 0.f;
        for (int c = lane; c < C; c += 32) s += conv_b[c] * proj_w[c];
        #pragma unroll
        for (int o = 16; o; o >>= 1) s += __shfl_down_sync(0xffffffffu, s, o);
        if (lane == 0) g_beff = s + proj_b[0];
    }
}

// ---------------- kernel 2: conv logits — cp.async staged tile ---------------
__global__ void __launch_bounds__(256, 2)
k_logit(const float* __restrict__ eouts) {
    extern __shared__ float sm[];           // SM_FLOATS floats
    int b = blockIdx.y;
    int t0 = blockIdx.x * TILE;
    int tid = threadIdx.x;  // 0..255

    // ---- stage: 42 rows x 128 chunks of 16B, all loads in flight ----
    {
        uint32_t sbase = smem_u32(sm);
        #pragma unroll
        for (int c = tid; c < NROWS * 128; c += 256) {
            int row = c >> 7;
            int off16 = c & 127;
            int t = t0 + row - KHALF;
            uint32_t saddr = sbase + c * 16;
            if (t >= 0 && t < T) {
                const float* g = eouts + ((size_t)b * T + t) * D + off16 * 4;
                asm volatile("cp.async.cg.shared.global [%0], [%1], 16;"
                             :: "r"(saddr), "l"(g));
            } else {
                asm volatile("st.shared.v4.b32 [%0], {%1, %1, %1, %1};"
                             :: "r"(saddr), "r"(0u));
            }
        }
        asm volatile("cp.async.commit_group;");
        asm volatile("cp.async.wait_group 0;");
    }
    __syncthreads();

    unsigned long long w[KW];
    #pragma unroll
    for (int k = 0; k < KW; k++) {
        float2 wv = ((const float2*)(g_weff + k * D))[tid];
        w[k] = pack2(wv.x, wv.y);
    }

    unsigned long long acc[TILE];
    unsigned long long z = pack2(0.f, 0.f);
    #pragma unroll
    for (int i = 0; i < TILE; i++) acc[i] = z;

    const unsigned long long* sm2 = (const unsigned long long*)sm;
    #pragma unroll
    for (int tt = 0; tt < NROWS; tt++) {
        unsigned long long vp = sm2[tt * 256 + tid];   // LDS.64, CF
        #pragma unroll
        for (int k = 0; k < KW; k++) {
            int i = tt - k;
            if (i >= 0 && i < TILE) FMA2(acc[i], vp, w[k]);
        }
    }
    __syncthreads();   // staging data consumed; reuse smem for reduction

    float* r  = sm;                 // [TILE][257]
    float* r2 = sm + TILE * 257;    // [TILE][9]
    #pragma unroll
    for (int i = 0; i < TILE; i++) {
        float lo, hi;
        unpack2(acc[i], lo, hi);
        r[i * 257 + tid] = lo + hi;
    }
    __syncthreads();
    {
        int i = tid & 31, seg = tid >> 5;   // 32 outputs x 8 segments of 32
        float sum = 0.f;
        #pragma unroll
        for (int j = 0; j < 32; j++)
            sum += r[i * 257 + seg * 32 + j];
        r2[i * 9 + seg] = sum;
    }
    __syncthreads();
    if (tid < TILE) {
        float tot = g_beff;
        #pragma unroll
        for (int j = 0; j < 8; j++) tot += r2[tid * 9 + j];
        g_logit[b * T + t0 + tid] = tot;
    }
}

// ---------------- kernel 3: alpha + prefix + prefetch-overlapped sweep -------
__global__ void k_alpha_scan(float* __restrict__ out_alpha,
                             const int* __restrict__ elens,
                             const int* __restrict__ ylens) {
    int b = blockIdx.x;
    int tid = threadIdx.x;
    int lane = tid & 31, wid = tid >> 5;

    __shared__ float  sA[T];        // alpha_norm
    __shared__ double sS[T];        // inclusive prefix of alpha_norm (exact)
    __shared__ double sT1[T];       // 1.0 - (double)alpha_norm
    __shared__ double sWarp[32];
    __shared__ int    s_fire_t[MAXTOK];
    __shared__ float  s_ak1[MAXTOK], s_ak2[MAXTOK];
    __shared__ float  s_asum;

    int el = elens[b];
    int yl = ylens[b];

    // --- step 1: sigmoid alphas + block reduce for asum ---
    float a0, a1;
    {
        double local = 0.0;
        #pragma unroll
        for (int rep = 0; rep < 2; rep++) {
            int t = tid + rep * 1024;
            float lg = g_logit[b * T + t];
            float a = 1.f / (1.f + expf(-lg));
            if (rep == 0) a0 = a; else a1 = a;
            local += (double)a;
        }
        #pragma unroll
        for (int o = 16; o; o >>= 1) local += __shfl_down_sync(0xffffffffu, local, o);
        if (lane == 0) sWarp[wid] = local;
        __syncthreads();
        if (wid == 0) {
            double v = sWarp[lane];
            #pragma unroll
            for (int o = 16; o; o >>= 1) v += __shfl_down_sync(0xffffffffu, v, o);
            if (lane == 0) s_asum = (float)v;
        }
        __syncthreads();
    }
    float asum = s_asum;
    float ylf = (float)yl;

    // --- step 2: alpha_norm + (1 - a) table ---
    {
        int t0 = tid, t1 = tid + 1024;
        float an0 = a0 / asum * ylf;
        float an1 = a1 / asum * ylf;
        sA[t0] = an0; sA[t1] = an1;
        sT1[t0] = 1.0 - (double)an0;
        sT1[t1] = 1.0 - (double)an1;
        out_alpha[b * T + t0] = a0;  out_alpha[b * T + t1] = a1;
        g_anorm[b * T + t0] = an0;   g_anorm[b * T + t1] = an1;
    }
    __syncthreads();

    // --- step 3: block inclusive prefix scan (double) ---
    {
        float e0 = sA[2 * tid], e1 = sA[2 * tid + 1];
        double my = (double)e0 + (double)e1;
        double v = my;
        #pragma unroll
        for (int o = 1; o < 32; o <<= 1) {
            double n = __shfl_up_sync(0xffffffffu, v, o);
            if (lane >= o) v += n;
        }
        if (lane == 31) sWarp[wid] = v;
        __syncthreads();
        if (wid == 0) {
            double w = sWarp[lane];
            #pragma unroll
            for (int o = 1; o < 32; o <<= 1) {
                double n = __shfl_up_sync(0xffffffffu, w, o);
                if (lane >= o) w += n;
            }
            sWarp[lane] = w;
        }
        __syncthreads();
        double base = (wid ? sWarp[wid - 1] : 0.0) + (v - my);
        sS[2 * tid]     = base + (double)e0;
        sS[2 * tid + 1] = base + (double)e0 + (double)e1;
    }
    __syncthreads();

    // --- step 4: warp 0 — prefetch-overlapped minimal-chain sweep ---
    // Same math as the pure-double R13 sweep (identical fire set + outputs);
    // loop restructured so the next probe's LDS and sT1[f] issue in parallel
    // BEFORE the th update, keeping only DADD->DSETP->ballot on the chain.
    if (wid == 0) {
        double th = (double)THRESH;
        int pos = 0, ntok = 0;
        // preloaded probe value for window starting at pos
        int t0i = lane;
        double v = sS[(t0i < T) ? t0i : (T - 1)];
        while (ntok < yl && pos < el) {
            int t = pos + lane;
            unsigned m = __ballot_sync(~0u, (t < el) && (v >= th));
            if (!m) {
                pos += 32;
                int u = pos + lane;
                v = sS[(u < T) ? u : (T - 1)];   // prefetch next window
                continue;
            }
            int f = pos + __ffs(m) - 1;
            // issue both loads immediately (parallel, off the DADD chain)
            double t1d = sT1[f];
            double Sf  = sS[f];
            pos = f + 1;
            {   // prefetch next window before th update
                int u = pos + lane;
                v = sS[(u < T) ? u : (T - 1)];
            }
            // off-chain token math (reference-identical float formulas)
            float a = sA[f];
            float acc = (float)(Sf - th) + THRESH;
            float ak1 = 1.f - acc;
            float ak2 = a - ak1;
            if (lane == 0) {
                s_fire_t[ntok] = f;
                s_ak1[ntok] = ak1;
                s_ak2[ntok] = ak2;
            }
            th += t1d;                   // the only chained FP64 op
            ntok++;
        }
        __syncwarp();
        if (lane == 0) g_nf[b] = ntok;
        for (int i = lane; i < ntok; i += 32) {
            g_fire_t[b * MAXTOK + i] = s_fire_t[i];
            g_fak1[b * MAXTOK + i] = s_ak1[i];
            g_fak2[b * MAXTOK + i] = s_ak2[i];
        }
    }
}

// ---------------- kernel 4: fused aws rows + fired reductions ----------------
// grid (L+1, B, 2): z=0 -> fired token n=x (x<L); z=1 -> aws row r=x.
__global__ void __launch_bounds__(1024)
k_out(const float* __restrict__ eouts, float* __restrict__ fired,
      float* __restrict__ aws, const int* __restrict__ elens,
      const int* __restrict__ ylens, int L) {
    int b = blockIdx.y;
    int nf = g_nf[b];

    if (blockIdx.z == 1) {
        // ---- aws row r ----
        int r = blockIdx.x;          // 0..L
        int tid = threadIdx.x;
        float4* row = (float4*)(aws + ((size_t)b * (L + 1) + r) * T);
        if (tid >= T / 4) return;
        if (r > nf) {
            row[tid] = make_float4(0.f, 0.f, 0.f, 0.f);
            return;
        }
        int el = elens[b];
        int yl = ylens[b];
        int   fprev = (r > 0) ? g_fire_t[b * MAXTOK + r - 1] : -1;
        float vprev = (r > 0) ? g_fak2[b * MAXTOK + r - 1] : 0.f;
        int   fr   = (r < nf) ? g_fire_t[b * MAXTOK + r] : -2;
        float vak1 = (r < nf) ? g_fak1[b * MAXTOK + r] : 0.f;
        int aEnd = (r < nf) ? fr : ((r < yl) ? el : fprev);

        const float4* an4 = (const float4*)(g_anorm + b * T);
        float4 a4 = an4[tid];
        float av[4] = {a4.x, a4.y, a4.z, a4.w};
        float ov[4];
        int t0 = 4 * tid;
        #pragma unroll
        for (int j = 0; j < 4; j++) {
            int t = t0 + j;
            float v = 0.f;
            if (t > fprev && t < aEnd) v = av[j];
            else if (t == fprev)       v = vprev;
            else if (t == fr)          v = vak1;
            ov[j] = v;
        }
        row[tid] = make_float4(ov[0], ov[1], ov[2], ov[3]);
        return;
    }

    // ---- fired token n (8-phase) ----
    int n = blockIdx.x;
    if (n >= L) return;
    int d  = threadIdx.x & 127;   // float4 slice of D
    int ph = threadIdx.x >> 7;    // 0..7 time phase

    if (n >= nf) {                // zero-fill unused rows
        if (ph == 0)
            ((float4*)(fired + ((size_t)b * L + n) * D))[d] =
                make_float4(0.f, 0.f, 0.f, 0.f);
        return;
    }

    int e = g_fire_t[b * MAXTOK + n];
    float c1 = g_fak1[b * MAXTOK + n];
    int s; float c0;
    if (n == 0) { s = -1; c0 = 0.f; }
    else { s = g_fire_t[b * MAXTOK + n - 1]; c0 = g_fak2[b * MAXTOK + n - 1]; }

    const float* an = g_anorm + b * T;
    const float4* eb = (const float4*)(eouts + (size_t)b * T * D);

    int t0 = (s >= 0) ? s : 0;
    float4 acc = make_float4(0.f, 0.f, 0.f, 0.f);
    #pragma unroll 2
    for (int t = t0 + ph; t <= e; t += 8) {
        float w = (t == e) ? c1 : ((t == s) ? c0 : an[t]);
        float4 v = eb[(size_t)t * 128 + d];
        acc.x += w * v.x; acc.y += w * v.y;
        acc.z += w * v.z; acc.w += w * v.w;
    }

    __shared__ float4 sAcc[1024];
    sAcc[threadIdx.x] = acc;
    __syncthreads();
    if (ph == 0) {
        #pragma unroll
        for (int p = 1; p < 8; p++) {
            float4 a = sAcc[p * 128 + d];
            acc.x += a.x; acc.y += a.y; acc.z += a.z; acc.w += a.w;
        }
        ((float4*)(fired + ((size_t)b * L + n) * D))[d] = acc;
    }
}

// ---------------- launch ------------------------------------------------------
extern "C" void kernel_launch(void* const* d_in, const int* in_sizes, int n_in,
                              void* d_out, int out_size) {
    const float* eouts  = (const float*)d_in[0];
    const float* conv_w = (const float*)d_in[1];
    const float* conv_b = (const float*)d_in[2];
    const float* proj_w = (const float*)d_in[3];
    const float* proj_b = (const float*)d_in[4];
    const int*   elens  = (const int*)d_in[5];
    const int*   ylens  = (const int*)d_in[6];

    // out = concat(fired[B,L,D], alpha[B,T], aws[B,1,L+1,T])
    int L = (out_size - 2 * B * T) / (B * D + B * T);

    float* out   = (float*)d_out;
    float* fired = out;
    float* alpha = out + (size_t)B * L * D;
    float* aws   = alpha + (size_t)B * T;

    const int SMEM_BYTES = SM_FLOATS * sizeof(float);  // 86016
    cudaFuncSetAttribute(k_logit,
                         cudaFuncAttributeMaxDynamicSharedMemorySize, SMEM_BYTES);

    k_weff<<<(KW * D + 1 + 7) / 8, 256>>>(conv_w, conv_b, proj_w, proj_b);
    k_logit<<<dim3(T / TILE, B), 256, SMEM_BYTES>>>(eouts);
    k_nop<<<1, 32>>>();
    k_alpha_scan<<<B, 1024>>>(alpha, elens, ylens);   // 4th launch -> profiled
    k_out<<<dim3(L + 1, B, 2), 1024>>>(eouts, fired, aws, elens, ylens, L);
}